// round 13
// baseline (speedup 1.0000x reference)
#include <cuda_runtime.h>
#include <cuda_bf16.h>
#include <cuda_fp16.h>
#include <cstdint>

#define NN   50000
#define NE   800000
#define FDIM 128
#define FOUT 16
#define NEG  0.2f
#define SCAN_B 512
#define NSCANB ((NN + SCAN_B - 1) / SCAN_B)   // 98

// gemm smem (bytes): A only; row stride = 136 bf16 = 272 B
#define SA_HI 0
#define SA_LO 34816
#define GEMM_SMEM 69632

// ---------------- scratch ----------------
__device__ __align__(16) float g_bufA[NN * FDIM];   // layer1/2 h stored as fp16 (reinterpreted)
__device__ __align__(16) float g_bufB[NN * FDIM];
__device__ __align__(16) float g_h3[NN * FOUT];
__device__ __align__(16) float g_es[NN * 4];
__device__ __align__(16) float g_ed[NN * 4];
__device__ __align__(16) uint32_t g_wfHi[16384];   // W fragments (2 layers), hi bf16
__device__ __align__(16) uint32_t g_wfLo[16384];   // W fragments (2 layers), lo bf16
__device__ int g_src[NE];
__device__ int g_dst[NE];
__device__ int g_deg[NN];
__device__ int g_rowptr[NN + 1];
__device__ int g_cursor[NN];
__device__ int g_csrc[NE];
__device__ int g_bsum[128];
__device__ int g_is32;

__device__ __forceinline__ void split2(float x, float y, uint32_t& h, uint32_t& l) {
    __nv_bfloat16 hx = __float2bfloat16(x), hy = __float2bfloat16(y);
    __nv_bfloat16 lx = __float2bfloat16(x - __bfloat162float(hx));
    __nv_bfloat16 ly = __float2bfloat16(y - __bfloat162float(hy));
    h = ((uint32_t)__bfloat16_as_ushort(hy) << 16) | __bfloat16_as_ushort(hx);
    l = ((uint32_t)__bfloat16_as_ushort(ly) << 16) | __bfloat16_as_ushort(lx);
}

__device__ __forceinline__ void mma_bf16(float* c, const uint32_t* a, uint32_t b0, uint32_t b1) {
    asm volatile(
        "mma.sync.aligned.m16n8k16.row.col.f32.bf16.bf16.f32 "
        "{%0,%1,%2,%3}, {%4,%5,%6,%7}, {%8,%9}, {%0,%1,%2,%3};"
        : "+f"(c[0]), "+f"(c[1]), "+f"(c[2]), "+f"(c[3])
        : "r"(a[0]), "r"(a[1]), "r"(a[2]), "r"(a[3]), "r"(b0), "r"(b1));
}

// ---- setup: zero degree + dtype detect + pack W1/W2 mma fragments ----
__global__ void k_setup(const int* __restrict__ ei,
                        const float* __restrict__ W1, const float* __restrict__ W2)
{
    int i = blockIdx.x * blockDim.x + threadIdx.x;
    if (i < NN) g_deg[i] = 0;
    if (i == 0) {
        int nz = 0;
#pragma unroll
        for (int t = 0; t < 16; t++) nz |= ei[2 * t + 1];
        g_is32 = (nz != 0);
    }
    if (i < 16384) {
        const float* W = (i < 8192) ? W1 : W2;
        int idx = i & 8191;
        int reg = idx & 1, lane = (idx >> 1) & 31;
        int rest = idx >> 6, nb = rest & 15, ks = rest >> 4;
        int g = lane >> 2, t = lane & 3;
        int n = nb * 8 + g;
        int k0 = ks * 16 + 2 * t + reg * 8;
        float w0 = W[k0 * 128 + n];
        float w1 = W[(k0 + 1) * 128 + n];
        uint32_t h, l;
        split2(w0, w1, h, l);
        g_wfHi[i] = h;
        g_wfLo[i] = l;
    }
}

__global__ void k_convert(const int* __restrict__ ei) {
    int e = blockIdx.x * blockDim.x + threadIdx.x;
    if (e >= NE) return;
    int s, d;
    if (g_is32) {
        s = ei[e]; d = ei[NE + e];
    } else {
        const long long* ell = (const long long*)ei;
        s = (int)ell[e]; d = (int)ell[NE + e];
    }
    g_src[e] = s;
    g_dst[e] = d;
    atomicAdd(&g_deg[d], 1);
}

// ---------------- exclusive scan ----------------
__global__ void k_scan1() {
    __shared__ int sm[SCAN_B];
    int i = blockIdx.x * SCAN_B + threadIdx.x;
    int v = (i < NN) ? g_deg[i] : 0;
    sm[threadIdx.x] = v;
    __syncthreads();
#pragma unroll
    for (int off = 1; off < SCAN_B; off <<= 1) {
        int t = (threadIdx.x >= off) ? sm[threadIdx.x - off] : 0;
        __syncthreads();
        sm[threadIdx.x] += t;
        __syncthreads();
    }
    if (i < NN) g_rowptr[i] = sm[threadIdx.x] - v;
    if (threadIdx.x == SCAN_B - 1) g_bsum[blockIdx.x] = sm[SCAN_B - 1];
}

__global__ void k_scan3() {
    __shared__ int pre[NSCANB];
    if (threadIdx.x < NSCANB) pre[threadIdx.x] = g_bsum[threadIdx.x];
    __syncthreads();
    if (threadIdx.x == 0) {
        int run = 0;
#pragma unroll 1
        for (int b = 0; b < NSCANB; b++) { int t = pre[b]; pre[b] = run; run += t; }
    }
    __syncthreads();
    int i = blockIdx.x * blockDim.x + threadIdx.x;
    if (i < NN) {
        int v = g_rowptr[i] + pre[i / SCAN_B];
        g_rowptr[i] = v;
        g_cursor[i] = v;
    }
    if (i == 0) g_rowptr[NN] = NE;
}

__global__ void k_fill() {
    int e = blockIdx.x * blockDim.x + threadIdx.x;
    if (e >= NE) return;
    int pos = atomicAdd(&g_cursor[g_dst[e]], 1);
    g_csrc[pos] = g_src[e];
}

// ------- tensor-core GEMM: h(fp16)[M,128] = A[M,128] @ W; bf16 split 3-product
// B fragments read via LDG (L1/L2-resident, lane-coalesced). A in smem only.
__global__ __launch_bounds__(256, 2) void k_gemm128_mma(
    const float* __restrict__ A, __half* __restrict__ C, int M,
    const float* __restrict__ a_s, const float* __restrict__ a_d, int slot)
{
    extern __shared__ char smem[];
    const int tid = threadIdx.x;
    const int rowBase = blockIdx.x * 128;

    // ---- load A tile, split into hi/lo bf16, padded rows (272B stride) ----
    {
        int r = tid & 127, half = tid >> 7;
        int gr = rowBase + r;
        const float* Ap = A + (long)gr * 128 + half * 64;
        char* ah = smem + SA_HI + r * 272 + half * 128;
        char* al = smem + SA_LO + r * 272 + half * 128;
#pragma unroll
        for (int q = 0; q < 8; q++) {
            float4 f0 = (gr < M) ? *(const float4*)(Ap + q * 8)     : make_float4(0,0,0,0);
            float4 f1 = (gr < M) ? *(const float4*)(Ap + q * 8 + 4) : make_float4(0,0,0,0);
            uint4 h, l;
            split2(f0.x, f0.y, h.x, l.x);
            split2(f0.z, f0.w, h.y, l.y);
            split2(f1.x, f1.y, h.z, l.z);
            split2(f1.z, f1.w, h.w, l.w);
            *(uint4*)(ah + q * 16) = h;
            *(uint4*)(al + q * 16) = l;
        }
    }
    __syncthreads();

    const int w = tid >> 5, lane = tid & 31;
    const int g = lane >> 2, t = lane & 3;
    const int mrow = (w >> 1) * 32;
    const int nbB  = (w & 1) * 8;

    float acc[2][8][4];
#pragma unroll
    for (int mb = 0; mb < 2; mb++)
#pragma unroll
        for (int nb = 0; nb < 8; nb++)
#pragma unroll
            for (int q = 0; q < 4; q++) acc[mb][nb][q] = 0.f;

    // per-warp B fragment base: word index (nbB*32 + lane)*2 within slot
    const uint32_t fragBase = (uint32_t)(slot * 8192 + (nbB * 32 + lane) * 2);

#pragma unroll
    for (int p = 0; p < 3; p++) {
        const char* Aarr = smem + (p == 2 ? SA_LO : SA_HI);
        const uint2* Bp = (const uint2*)((p == 1 ? g_wfLo : g_wfHi) + fragBase);
#pragma unroll
        for (int ks = 0; ks < 8; ks++) {
            uint32_t a[2][4];
#pragma unroll
            for (int mb = 0; mb < 2; mb++) {
                int r0 = mrow + mb * 16 + g;
                int kb = (ks * 16 + 2 * t) * 2;
                a[mb][0] = *(const uint32_t*)(Aarr + r0 * 272 + kb);
                a[mb][1] = *(const uint32_t*)(Aarr + (r0 + 8) * 272 + kb);
                a[mb][2] = *(const uint32_t*)(Aarr + r0 * 272 + kb + 16);
                a[mb][3] = *(const uint32_t*)(Aarr + (r0 + 8) * 272 + kb + 16);
            }
#pragma unroll
            for (int nb = 0; nb < 8; nb++) {
                // word offset for (ks, nb): (ks*16 + nb)*32 words of uint2
                uint2 b = __ldg(Bp + (ks * 16 + nb) * 32);
                mma_bf16(acc[0][nb], a[0], b.x, b.y);
                mma_bf16(acc[1][nb], a[1], b.x, b.y);
            }
        }
    }

    // ---- epilogue: store C (fp16) + fused es/ed (from fp32 accs) ----
    float es[2][2][2], ed[2][2][2];
#pragma unroll
    for (int mb = 0; mb < 2; mb++)
#pragma unroll
        for (int rh = 0; rh < 2; rh++)
#pragma unroll
            for (int h = 0; h < 2; h++) { es[mb][rh][h] = 0.f; ed[mb][rh][h] = 0.f; }

#pragma unroll
    for (int mb = 0; mb < 2; mb++) {
        int r0 = rowBase + mrow + mb * 16 + g;
        int r1 = r0 + 8;
#pragma unroll
        for (int nb = 0; nb < 8; nb++) {
            int col = (w & 1) * 64 + nb * 8 + 2 * t;
            int h = nb >> 2;
            float c0 = acc[mb][nb][0], c1 = acc[mb][nb][1];
            float c2 = acc[mb][nb][2], c3 = acc[mb][nb][3];
            if (r0 < M) *(__half2*)(C + (long)r0 * 128 + col) = __floats2half2_rn(c0, c1);
            if (r1 < M) *(__half2*)(C + (long)r1 * 128 + col) = __floats2half2_rn(c2, c3);
            float as0 = a_s[col], as1 = a_s[col + 1];
            float ad0 = a_d[col], ad1 = a_d[col + 1];
            es[mb][0][h] += c0 * as0 + c1 * as1;
            es[mb][1][h] += c2 * as0 + c3 * as1;
            ed[mb][0][h] += c0 * ad0 + c1 * ad1;
            ed[mb][1][h] += c2 * ad0 + c3 * ad1;
        }
    }
#pragma unroll
    for (int mb = 0; mb < 2; mb++)
#pragma unroll
        for (int rh = 0; rh < 2; rh++)
#pragma unroll
            for (int h = 0; h < 2; h++) {
                float s = es[mb][rh][h], d = ed[mb][rh][h];
                s += __shfl_xor_sync(0xffffffff, s, 1);
                d += __shfl_xor_sync(0xffffffff, d, 1);
                s += __shfl_xor_sync(0xffffffff, s, 2);
                d += __shfl_xor_sync(0xffffffff, d, 2);
                if (t == 0) {
                    int row = rowBase + mrow + mb * 16 + rh * 8 + g;
                    if (row < M) {
                        int head = (w & 1) * 2 + h;
                        g_es[row * 4 + head] = s;
                        g_ed[row * 4 + head] = d;
                    }
                }
            }
}

// ---------------- layer-3 GEMM + fused attn (H=1, C=16), fp32 ----------------
__global__ __launch_bounds__(256) void k_gemm16(
    const float* __restrict__ A, const float* __restrict__ W,
    float* __restrict__ C, int M,
    const float* __restrict__ a_s, const float* __restrict__ a_d)
{
    __shared__ float Ws[128 * 16];
    int tid = threadIdx.x;
    for (int i = tid * 4; i < 2048; i += 1024)
        *(float4*)&Ws[i] = *(const float4*)(W + i);
    __syncthreads();
    int row = blockIdx.x * 64 + (tid >> 2);
    int c4 = (tid & 3) * 4;
    if (row >= M) return;
    const float* Ap = A + (long)row * 128;
    float4 acc = make_float4(0, 0, 0, 0);
#pragma unroll 8
    for (int k = 0; k < 128; k += 4) {
        float4 a = *(const float4*)(Ap + k);
#pragma unroll
        for (int kk = 0; kk < 4; kk++) {
            float av = (&a.x)[kk];
            float4 w = *(const float4*)&Ws[(k + kk) * 16 + c4];
            acc.x += av * w.x; acc.y += av * w.y;
            acc.z += av * w.z; acc.w += av * w.w;
        }
    }
    *(float4*)(C + (long)row * 16 + c4) = acc;

    float4 u = *(const float4*)(a_s + c4);
    float4 v = *(const float4*)(a_d + c4);
    float s = acc.x * u.x + acc.y * u.y + acc.z * u.z + acc.w * u.w;
    float d = acc.x * v.x + acc.y * v.y + acc.z * v.z + acc.w * v.w;
    s += __shfl_xor_sync(0xffffffff, s, 1);
    d += __shfl_xor_sync(0xffffffff, d, 1);
    s += __shfl_xor_sync(0xffffffff, s, 2);
    d += __shfl_xor_sync(0xffffffff, d, 2);
    if ((tid & 3) == 0) { g_es[row] = s; g_ed[row] = d; }
}

// ------- fused gather, warp per dst; h is fp16; csrc batched via shfl -------
template<bool RELU>
__global__ void k_gather128(const __half* __restrict__ h, float* __restrict__ o,
                            const float* __restrict__ bias)
{
    int w = (blockIdx.x * blockDim.x + threadIdx.x) >> 5;
    int lane = threadIdx.x & 31;
    if (w >= NN) return;
    int head = lane >> 3;
    float edh = g_ed[w * 4 + head];
    float denom = 0.f;
    float4 acc = make_float4(0, 0, 0, 0);
    {
        float v = g_es[w * 4 + head] + edh;
        v = (v > 0.f) ? v : NEG * v;
        float p = __expf(v);
        denom += p;
        uint2 raw = *(const uint2*)(h + (long)w * 128 + lane * 4);
        float2 f01 = __half22float2(*(__half2*)&raw.x);
        float2 f23 = __half22float2(*(__half2*)&raw.y);
        acc.x += p * f01.x; acc.y += p * f01.y; acc.z += p * f23.x; acc.w += p * f23.y;
    }
    int j = g_rowptr[w], end = g_rowptr[w + 1];
    while (j < end) {
        int rem = end - j;
        int batch = rem < 32 ? rem : 32;
        int s_l = (lane < batch) ? g_csrc[j + lane] : 0;
        int t = 0;
        for (; t + 2 <= batch; t += 2) {
            int s0 = __shfl_sync(0xffffffff, s_l, t);
            int s1 = __shfl_sync(0xffffffff, s_l, t + 1);
            float v0 = g_es[s0 * 4 + head] + edh;
            float v1 = g_es[s1 * 4 + head] + edh;
            uint2 r0 = *(const uint2*)(h + (long)s0 * 128 + lane * 4);
            uint2 r1 = *(const uint2*)(h + (long)s1 * 128 + lane * 4);
            v0 = (v0 > 0.f) ? v0 : NEG * v0;
            v1 = (v1 > 0.f) ? v1 : NEG * v1;
            float p0 = __expf(v0), p1 = __expf(v1);
            denom += p0 + p1;
            float2 a01 = __half22float2(*(__half2*)&r0.x);
            float2 a23 = __half22float2(*(__half2*)&r0.y);
            float2 b01 = __half22float2(*(__half2*)&r1.x);
            float2 b23 = __half22float2(*(__half2*)&r1.y);
            acc.x += p0 * a01.x + p1 * b01.x;
            acc.y += p0 * a01.y + p1 * b01.y;
            acc.z += p0 * a23.x + p1 * b23.x;
            acc.w += p0 * a23.y + p1 * b23.y;
        }
        if (t < batch) {
            int s = __shfl_sync(0xffffffff, s_l, t);
            float v = g_es[s * 4 + head] + edh;
            v = (v > 0.f) ? v : NEG * v;
            float p = __expf(v);
            denom += p;
            uint2 raw = *(const uint2*)(h + (long)s * 128 + lane * 4);
            float2 f01 = __half22float2(*(__half2*)&raw.x);
            float2 f23 = __half22float2(*(__half2*)&raw.y);
            acc.x += p * f01.x; acc.y += p * f01.y; acc.z += p * f23.x; acc.w += p * f23.y;
        }
        j += batch;
    }
    float inv = 1.f / (denom + 1e-16f);
    float4 b = *(const float4*)(bias + lane * 4);
    float4 r;
    r.x = acc.x * inv + b.x; r.y = acc.y * inv + b.y;
    r.z = acc.z * inv + b.z; r.w = acc.w * inv + b.w;
    if (RELU) {
        r.x = fmaxf(r.x, 0.f); r.y = fmaxf(r.y, 0.f);
        r.z = fmaxf(r.z, 0.f); r.w = fmaxf(r.w, 0.f);
    }
    *(float4*)(o + (long)w * 128 + lane * 4) = r;
}

// ---- fused gather (F=16, H=1): quad per dst, fp32 h ------------------------
__global__ void k_gather16(const float* __restrict__ h, float* __restrict__ o,
                           const float* __restrict__ bias)
{
    int g = blockIdx.x * blockDim.x + threadIdx.x;
    int n = g >> 2, q = g & 3;
    if (n >= NN) return;
    int lane = threadIdx.x & 31;
    int qbase = lane & 28;
    unsigned qmask = 0xFu << qbase;
    float edh = g_ed[n];
    float denom = 0.f;
    float4 acc = make_float4(0, 0, 0, 0);
    {
        float v = g_es[n] + edh;
        v = (v > 0.f) ? v : NEG * v;
        float p = __expf(v);
        denom += p;
        float4 hv = *(const float4*)(h + (long)n * 16 + q * 4);
        acc.x += p * hv.x; acc.y += p * hv.y; acc.z += p * hv.z; acc.w += p * hv.w;
    }
    int j = g_rowptr[n], end = g_rowptr[n + 1];
    while (j < end) {
        int rem = end - j;
        int batch = rem < 4 ? rem : 4;
        int s_l = (q < batch) ? g_csrc[j + q] : 0;
#pragma unroll 4
        for (int t = 0; t < batch; t++) {
            int s = __shfl_sync(qmask, s_l, qbase + t);
            float v = g_es[s] + edh;
            v = (v > 0.f) ? v : NEG * v;
            float p = __expf(v);
            denom += p;
            float4 hv = *(const float4*)(h + (long)s * 16 + q * 4);
            acc.x += p * hv.x; acc.y += p * hv.y; acc.z += p * hv.z; acc.w += p * hv.w;
        }
        j += batch;
    }
    float inv = 1.f / (denom + 1e-16f);
    float4 b = *(const float4*)(bias + q * 4);
    float4 r;
    r.x = acc.x * inv + b.x; r.y = acc.y * inv + b.y;
    r.z = acc.z * inv + b.z; r.w = acc.w * inv + b.w;
    *(float4*)(o + (long)n * 16 + q * 4) = r;
}

// ---------------- launch ----------------
extern "C" void kernel_launch(void* const* d_in, const int* in_sizes, int n_in,
                              void* d_out, int out_size)
{
    const float* x   = (const float*)d_in[0];
    const int*   ei  = (const int*)d_in[1];
    const float* W1  = (const float*)d_in[2];
    const float* as1 = (const float*)d_in[3];
    const float* ad1 = (const float*)d_in[4];
    const float* b1  = (const float*)d_in[5];
    const float* W2  = (const float*)d_in[6];
    const float* as2 = (const float*)d_in[7];
    const float* ad2 = (const float*)d_in[8];
    const float* b2  = (const float*)d_in[9];
    const float* W3  = (const float*)d_in[10];
    const float* as3 = (const float*)d_in[11];
    const float* ad3 = (const float*)d_in[12];
    const float* b3  = (const float*)d_in[13];
    float* out = (float*)d_out;

    float *bufA, *bufB, *h3;
    cudaGetSymbolAddress((void**)&bufA, g_bufA);
    cudaGetSymbolAddress((void**)&bufB, g_bufB);
    cudaGetSymbolAddress((void**)&h3,   g_h3);
    __half* hA = (__half*)bufA;

    cudaFuncSetAttribute(k_gemm128_mma,
                         cudaFuncAttributeMaxDynamicSharedMemorySize, GEMM_SMEM);

    const int T = 256;
    const int gGemm = (NN + 127) / 128;
    const int gWarp = (NN * 32 + T - 1) / T;
    const int gQuad = (NN * 4 + T - 1) / T;

    // 1-3: setup + CSR phase 1
    k_setup<<<(NN + T - 1) / T, T>>>(ei, W1, W2);
    k_convert<<<(NE + T - 1) / T, T>>>(ei);
    k_scan1<<<NSCANB, SCAN_B>>>();
    // 4: layer-1 GEMM (profiled slot)
    k_gemm128_mma<<<gGemm, T, GEMM_SMEM>>>(x, hA, NN, as1, ad1, 0);
    // 5-6: finish CSR
    k_scan3<<<(NN + T - 1) / T, T>>>();
    k_fill<<<(NE + T - 1) / T, T>>>();
    // layer 1 aggregate
    k_gather128<true><<<gWarp, T>>>(hA, bufB, b1);
    // layer 2
    k_gemm128_mma<<<gGemm, T, GEMM_SMEM>>>(bufB, hA, NN, as2, ad2, 1);
    k_gather128<true><<<gWarp, T>>>(hA, bufB, b2);
    // layer 3 (fp32)
    k_gemm16<<<(NN + 63) / 64, T>>>(bufB, W3, h3, NN, as3, ad3);
    k_gather16<<<gQuad, T>>>(h3, out, b3);
}

// round 14
// speedup vs baseline: 1.3706x; 1.3706x over previous
#include <cuda_runtime.h>
#include <cuda_bf16.h>
#include <cuda_fp16.h>
#include <cstdint>

#define NN   50000
#define NE   800000
#define FDIM 128
#define FOUT 16
#define NEG  0.2f
#define SCAN_B 512
#define NSCANB ((NN + SCAN_B - 1) / SCAN_B)   // 98

// gemm smem layout (bytes): A row stride = 136 bf16 = 272 B
#define SA_HI 0
#define SA_LO 34816
#define SB_HI 69632
#define SB_LO 102400
#define GEMM_SMEM 135168

// ---------------- scratch ----------------
__device__ __align__(16) float g_bufA[NN * FDIM];   // layer1/2 h stored as fp16 (reinterpreted)
__device__ __align__(16) float g_bufB[NN * FDIM];
__device__ __align__(16) float g_h3[NN * FOUT];
__device__ __align__(16) float g_es[NN * 4];
__device__ __align__(16) float g_ed[NN * 4];
__device__ __align__(16) uint32_t g_wfHi[16384];   // W fragments (2 layers), hi bf16
__device__ __align__(16) uint32_t g_wfLo[16384];   // W fragments (2 layers), lo bf16
__device__ int g_src[NE];
__device__ int g_dst[NE];
__device__ int g_deg[NN];
__device__ int g_rowptr[NN + 1];
__device__ int g_cursor[NN];
__device__ int g_csrc[NE];
__device__ int g_bsum[128];
__device__ int g_is32;

__device__ __forceinline__ void split2(float x, float y, uint32_t& h, uint32_t& l) {
    __nv_bfloat16 hx = __float2bfloat16(x), hy = __float2bfloat16(y);
    __nv_bfloat16 lx = __float2bfloat16(x - __bfloat162float(hx));
    __nv_bfloat16 ly = __float2bfloat16(y - __bfloat162float(hy));
    h = ((uint32_t)__bfloat16_as_ushort(hy) << 16) | __bfloat16_as_ushort(hx);
    l = ((uint32_t)__bfloat16_as_ushort(ly) << 16) | __bfloat16_as_ushort(lx);
}

__device__ __forceinline__ void mma_bf16(float* c, const uint32_t* a, uint32_t b0, uint32_t b1) {
    asm volatile(
        "mma.sync.aligned.m16n8k16.row.col.f32.bf16.bf16.f32 "
        "{%0,%1,%2,%3}, {%4,%5,%6,%7}, {%8,%9}, {%0,%1,%2,%3};"
        : "+f"(c[0]), "+f"(c[1]), "+f"(c[2]), "+f"(c[3])
        : "r"(a[0]), "r"(a[1]), "r"(a[2]), "r"(a[3]), "r"(b0), "r"(b1));
}

// ---- setup: zero degree + dtype detect + pack W1/W2 mma fragments ----
__global__ void k_setup(const int* __restrict__ ei,
                        const float* __restrict__ W1, const float* __restrict__ W2)
{
    int i = blockIdx.x * blockDim.x + threadIdx.x;
    if (i < NN) g_deg[i] = 0;
    if (i == 0) {
        int nz = 0;
#pragma unroll
        for (int t = 0; t < 16; t++) nz |= ei[2 * t + 1];
        g_is32 = (nz != 0);
    }
    if (i < 16384) {
        const float* W = (i < 8192) ? W1 : W2;
        int idx = i & 8191;
        int reg = idx & 1, lane = (idx >> 1) & 31;
        int rest = idx >> 6, nb = rest & 15, ks = rest >> 4;
        int g = lane >> 2, t = lane & 3;
        int n = nb * 8 + g;
        int k0 = ks * 16 + 2 * t + reg * 8;
        float w0 = W[k0 * 128 + n];
        float w1 = W[(k0 + 1) * 128 + n];
        uint32_t h, l;
        split2(w0, w1, h, l);
        g_wfHi[i] = h;
        g_wfLo[i] = l;
    }
}

__global__ void k_convert(const int* __restrict__ ei) {
    int e = blockIdx.x * blockDim.x + threadIdx.x;
    if (e >= NE) return;
    int s, d;
    if (g_is32) {
        s = ei[e]; d = ei[NE + e];
    } else {
        const long long* ell = (const long long*)ei;
        s = (int)ell[e]; d = (int)ell[NE + e];
    }
    g_src[e] = s;
    g_dst[e] = d;
    atomicAdd(&g_deg[d], 1);
}

// ---------------- exclusive scan ----------------
__global__ void k_scan1() {
    __shared__ int sm[SCAN_B];
    int i = blockIdx.x * SCAN_B + threadIdx.x;
    int v = (i < NN) ? g_deg[i] : 0;
    sm[threadIdx.x] = v;
    __syncthreads();
#pragma unroll
    for (int off = 1; off < SCAN_B; off <<= 1) {
        int t = (threadIdx.x >= off) ? sm[threadIdx.x - off] : 0;
        __syncthreads();
        sm[threadIdx.x] += t;
        __syncthreads();
    }
    if (i < NN) g_rowptr[i] = sm[threadIdx.x] - v;
    if (threadIdx.x == SCAN_B - 1) g_bsum[blockIdx.x] = sm[SCAN_B - 1];
}

__global__ void k_scan3() {
    __shared__ int pre[NSCANB];
    if (threadIdx.x < NSCANB) pre[threadIdx.x] = g_bsum[threadIdx.x];
    __syncthreads();
    if (threadIdx.x == 0) {
        int run = 0;
#pragma unroll 1
        for (int b = 0; b < NSCANB; b++) { int t = pre[b]; pre[b] = run; run += t; }
    }
    __syncthreads();
    int i = blockIdx.x * blockDim.x + threadIdx.x;
    if (i < NN) {
        int v = g_rowptr[i] + pre[i / SCAN_B];
        g_rowptr[i] = v;
        g_cursor[i] = v;
    }
    if (i == 0) g_rowptr[NN] = NE;
}

__global__ void k_fill() {
    int e = blockIdx.x * blockDim.x + threadIdx.x;
    if (e >= NE) return;
    int pos = atomicAdd(&g_cursor[g_dst[e]], 1);
    g_csrc[pos] = g_src[e];
}

// ------- tensor-core GEMM: h(fp16)[M,128] = A[M,128] @ W; bf16 split 3-product
// B fragments staged in smem (one-time copy), A in smem with padded rows.
__global__ __launch_bounds__(256, 1) void k_gemm128_mma(
    const float* __restrict__ A, __half* __restrict__ C, int M,
    const float* __restrict__ a_s, const float* __restrict__ a_d, int slot)
{
    extern __shared__ char smem[];
    const int tid = threadIdx.x;
    const int rowBase = blockIdx.x * 128;

    // ---- load A tile, split into hi/lo bf16, padded rows (272B stride) ----
    {
        int r = tid & 127, half = tid >> 7;
        int gr = rowBase + r;
        const float* Ap = A + (long)gr * 128 + half * 64;
        char* ah = smem + SA_HI + r * 272 + half * 128;
        char* al = smem + SA_LO + r * 272 + half * 128;
#pragma unroll
        for (int q = 0; q < 8; q++) {
            float4 f0 = (gr < M) ? *(const float4*)(Ap + q * 8)     : make_float4(0,0,0,0);
            float4 f1 = (gr < M) ? *(const float4*)(Ap + q * 8 + 4) : make_float4(0,0,0,0);
            uint4 h, l;
            split2(f0.x, f0.y, h.x, l.x);
            split2(f0.z, f0.w, h.y, l.y);
            split2(f1.x, f1.y, h.z, l.z);
            split2(f1.z, f1.w, h.w, l.w);
            *(uint4*)(ah + q * 16) = h;
            *(uint4*)(al + q * 16) = l;
        }
    }
    // ---- copy pre-packed W fragments (flat) ----
    {
        const uint4* sH = (const uint4*)(g_wfHi + slot * 8192);
        const uint4* sL = (const uint4*)(g_wfLo + slot * 8192);
        uint4* dH = (uint4*)(smem + SB_HI);
        uint4* dL = (uint4*)(smem + SB_LO);
        for (int q = tid; q < 2048; q += 256) { dH[q] = sH[q]; dL[q] = sL[q]; }
    }
    __syncthreads();

    const int w = tid >> 5, lane = tid & 31;
    const int g = lane >> 2, t = lane & 3;
    const int mrow = (w >> 1) * 32;
    const int nbB  = (w & 1) * 8;

    float acc[2][8][4];
#pragma unroll
    for (int mb = 0; mb < 2; mb++)
#pragma unroll
        for (int nb = 0; nb < 8; nb++)
#pragma unroll
            for (int q = 0; q < 4; q++) acc[mb][nb][q] = 0.f;

#pragma unroll
    for (int p = 0; p < 3; p++) {
        const char* Aarr = smem + (p == 2 ? SA_LO : SA_HI);
        const char* Barr = smem + (p == 1 ? SB_LO : SB_HI);
#pragma unroll
        for (int ks = 0; ks < 8; ks++) {
            uint32_t a[2][4];
#pragma unroll
            for (int mb = 0; mb < 2; mb++) {
                int r0 = mrow + mb * 16 + g;
                int kb = (ks * 16 + 2 * t) * 2;
                a[mb][0] = *(const uint32_t*)(Aarr + r0 * 272 + kb);
                a[mb][1] = *(const uint32_t*)(Aarr + (r0 + 8) * 272 + kb);
                a[mb][2] = *(const uint32_t*)(Aarr + r0 * 272 + kb + 16);
                a[mb][3] = *(const uint32_t*)(Aarr + (r0 + 8) * 272 + kb + 16);
            }
#pragma unroll
            for (int nb = 0; nb < 8; nb++) {
                uint2 b = *(const uint2*)(Barr + ((ks * 16 + nbB + nb) * 32 + lane) * 8);
                mma_bf16(acc[0][nb], a[0], b.x, b.y);
                mma_bf16(acc[1][nb], a[1], b.x, b.y);
            }
        }
    }

    // ---- epilogue: store C (fp16) + fused es/ed (from fp32 accs) ----
    float es[2][2][2], ed[2][2][2];
#pragma unroll
    for (int mb = 0; mb < 2; mb++)
#pragma unroll
        for (int rh = 0; rh < 2; rh++)
#pragma unroll
            for (int h = 0; h < 2; h++) { es[mb][rh][h] = 0.f; ed[mb][rh][h] = 0.f; }

#pragma unroll
    for (int mb = 0; mb < 2; mb++) {
        int r0 = rowBase + mrow + mb * 16 + g;
        int r1 = r0 + 8;
#pragma unroll
        for (int nb = 0; nb < 8; nb++) {
            int col = (w & 1) * 64 + nb * 8 + 2 * t;
            int h = nb >> 2;
            float c0 = acc[mb][nb][0], c1 = acc[mb][nb][1];
            float c2 = acc[mb][nb][2], c3 = acc[mb][nb][3];
            if (r0 < M) *(__half2*)(C + (long)r0 * 128 + col) = __floats2half2_rn(c0, c1);
            if (r1 < M) *(__half2*)(C + (long)r1 * 128 + col) = __floats2half2_rn(c2, c3);
            float as0 = a_s[col], as1 = a_s[col + 1];
            float ad0 = a_d[col], ad1 = a_d[col + 1];
            es[mb][0][h] += c0 * as0 + c1 * as1;
            es[mb][1][h] += c2 * as0 + c3 * as1;
            ed[mb][0][h] += c0 * ad0 + c1 * ad1;
            ed[mb][1][h] += c2 * ad0 + c3 * ad1;
        }
    }
#pragma unroll
    for (int mb = 0; mb < 2; mb++)
#pragma unroll
        for (int rh = 0; rh < 2; rh++)
#pragma unroll
            for (int h = 0; h < 2; h++) {
                float s = es[mb][rh][h], d = ed[mb][rh][h];
                s += __shfl_xor_sync(0xffffffff, s, 1);
                d += __shfl_xor_sync(0xffffffff, d, 1);
                s += __shfl_xor_sync(0xffffffff, s, 2);
                d += __shfl_xor_sync(0xffffffff, d, 2);
                if (t == 0) {
                    int row = rowBase + mrow + mb * 16 + rh * 8 + g;
                    if (row < M) {
                        int head = (w & 1) * 2 + h;
                        g_es[row * 4 + head] = s;
                        g_ed[row * 4 + head] = d;
                    }
                }
            }
}

// ---------------- layer-3 GEMM + fused attn (H=1, C=16), fp32 ----------------
__global__ __launch_bounds__(256) void k_gemm16(
    const float* __restrict__ A, const float* __restrict__ W,
    float* __restrict__ C, int M,
    const float* __restrict__ a_s, const float* __restrict__ a_d)
{
    __shared__ float Ws[128 * 16];
    int tid = threadIdx.x;
    for (int i = tid * 4; i < 2048; i += 1024)
        *(float4*)&Ws[i] = *(const float4*)(W + i);
    __syncthreads();
    int row = blockIdx.x * 64 + (tid >> 2);
    int c4 = (tid & 3) * 4;
    if (row >= M) return;
    const float* Ap = A + (long)row * 128;
    float4 acc = make_float4(0, 0, 0, 0);
#pragma unroll 8
    for (int k = 0; k < 128; k += 4) {
        float4 a = *(const float4*)(Ap + k);
#pragma unroll
        for (int kk = 0; kk < 4; kk++) {
            float av = (&a.x)[kk];
            float4 w = *(const float4*)&Ws[(k + kk) * 16 + c4];
            acc.x += av * w.x; acc.y += av * w.y;
            acc.z += av * w.z; acc.w += av * w.w;
        }
    }
    *(float4*)(C + (long)row * 16 + c4) = acc;

    float4 u = *(const float4*)(a_s + c4);
    float4 v = *(const float4*)(a_d + c4);
    float s = acc.x * u.x + acc.y * u.y + acc.z * u.z + acc.w * u.w;
    float d = acc.x * v.x + acc.y * v.y + acc.z * v.z + acc.w * v.w;
    s += __shfl_xor_sync(0xffffffff, s, 1);
    d += __shfl_xor_sync(0xffffffff, d, 1);
    s += __shfl_xor_sync(0xffffffff, s, 2);
    d += __shfl_xor_sync(0xffffffff, d, 2);
    if ((tid & 3) == 0) { g_es[row] = s; g_ed[row] = d; }
}

// ------- fused gather, warp per dst; h is fp16; csrc batched via shfl -------
template<bool RELU>
__global__ void k_gather128(const __half* __restrict__ h, float* __restrict__ o,
                            const float* __restrict__ bias)
{
    int w = (blockIdx.x * blockDim.x + threadIdx.x) >> 5;
    int lane = threadIdx.x & 31;
    if (w >= NN) return;
    int head = lane >> 3;
    float edh = g_ed[w * 4 + head];
    float denom = 0.f;
    float4 acc = make_float4(0, 0, 0, 0);
    {
        float v = g_es[w * 4 + head] + edh;
        v = (v > 0.f) ? v : NEG * v;
        float p = __expf(v);
        denom += p;
        uint2 raw = *(const uint2*)(h + (long)w * 128 + lane * 4);
        float2 f01 = __half22float2(*(__half2*)&raw.x);
        float2 f23 = __half22float2(*(__half2*)&raw.y);
        acc.x += p * f01.x; acc.y += p * f01.y; acc.z += p * f23.x; acc.w += p * f23.y;
    }
    int j = g_rowptr[w], end = g_rowptr[w + 1];
    while (j < end) {
        int rem = end - j;
        int batch = rem < 32 ? rem : 32;
        int s_l = (lane < batch) ? g_csrc[j + lane] : 0;
        int t = 0;
        for (; t + 2 <= batch; t += 2) {
            int s0 = __shfl_sync(0xffffffff, s_l, t);
            int s1 = __shfl_sync(0xffffffff, s_l, t + 1);
            float v0 = g_es[s0 * 4 + head] + edh;
            float v1 = g_es[s1 * 4 + head] + edh;
            uint2 r0 = *(const uint2*)(h + (long)s0 * 128 + lane * 4);
            uint2 r1 = *(const uint2*)(h + (long)s1 * 128 + lane * 4);
            v0 = (v0 > 0.f) ? v0 : NEG * v0;
            v1 = (v1 > 0.f) ? v1 : NEG * v1;
            float p0 = __expf(v0), p1 = __expf(v1);
            denom += p0 + p1;
            float2 a01 = __half22float2(*(__half2*)&r0.x);
            float2 a23 = __half22float2(*(__half2*)&r0.y);
            float2 b01 = __half22float2(*(__half2*)&r1.x);
            float2 b23 = __half22float2(*(__half2*)&r1.y);
            acc.x += p0 * a01.x + p1 * b01.x;
            acc.y += p0 * a01.y + p1 * b01.y;
            acc.z += p0 * a23.x + p1 * b23.x;
            acc.w += p0 * a23.y + p1 * b23.y;
        }
        if (t < batch) {
            int s = __shfl_sync(0xffffffff, s_l, t);
            float v = g_es[s * 4 + head] + edh;
            v = (v > 0.f) ? v : NEG * v;
            float p = __expf(v);
            denom += p;
            uint2 raw = *(const uint2*)(h + (long)s * 128 + lane * 4);
            float2 f01 = __half22float2(*(__half2*)&raw.x);
            float2 f23 = __half22float2(*(__half2*)&raw.y);
            acc.x += p * f01.x; acc.y += p * f01.y; acc.z += p * f23.x; acc.w += p * f23.y;
        }
        j += batch;
    }
    float inv = 1.f / (denom + 1e-16f);
    float4 b = *(const float4*)(bias + lane * 4);
    float4 r;
    r.x = acc.x * inv + b.x; r.y = acc.y * inv + b.y;
    r.z = acc.z * inv + b.z; r.w = acc.w * inv + b.w;
    if (RELU) {
        r.x = fmaxf(r.x, 0.f); r.y = fmaxf(r.y, 0.f);
        r.z = fmaxf(r.z, 0.f); r.w = fmaxf(r.w, 0.f);
    }
    *(float4*)(o + (long)w * 128 + lane * 4) = r;
}

// ---- fused gather (F=16, H=1): quad per dst, fp32 h ------------------------
__global__ void k_gather16(const float* __restrict__ h, float* __restrict__ o,
                           const float* __restrict__ bias)
{
    int g = blockIdx.x * blockDim.x + threadIdx.x;
    int n = g >> 2, q = g & 3;
    if (n >= NN) return;
    int lane = threadIdx.x & 31;
    int qbase = lane & 28;
    unsigned qmask = 0xFu << qbase;
    float edh = g_ed[n];
    float denom = 0.f;
    float4 acc = make_float4(0, 0, 0, 0);
    {
        float v = g_es[n] + edh;
        v = (v > 0.f) ? v : NEG * v;
        float p = __expf(v);
        denom += p;
        float4 hv = *(const float4*)(h + (long)n * 16 + q * 4);
        acc.x += p * hv.x; acc.y += p * hv.y; acc.z += p * hv.z; acc.w += p * hv.w;
    }
    int j = g_rowptr[n], end = g_rowptr[n + 1];
    while (j < end) {
        int rem = end - j;
        int batch = rem < 4 ? rem : 4;
        int s_l = (q < batch) ? g_csrc[j + q] : 0;
#pragma unroll 4
        for (int t = 0; t < batch; t++) {
            int s = __shfl_sync(qmask, s_l, qbase + t);
            float v = g_es[s] + edh;
            v = (v > 0.f) ? v : NEG * v;
            float p = __expf(v);
            denom += p;
            float4 hv = *(const float4*)(h + (long)s * 16 + q * 4);
            acc.x += p * hv.x; acc.y += p * hv.y; acc.z += p * hv.z; acc.w += p * hv.w;
        }
        j += batch;
    }
    float inv = 1.f / (denom + 1e-16f);
    float4 b = *(const float4*)(bias + q * 4);
    float4 r;
    r.x = acc.x * inv + b.x; r.y = acc.y * inv + b.y;
    r.z = acc.z * inv + b.z; r.w = acc.w * inv + b.w;
    *(float4*)(o + (long)n * 16 + q * 4) = r;
}

// ---------------- launch ----------------
extern "C" void kernel_launch(void* const* d_in, const int* in_sizes, int n_in,
                              void* d_out, int out_size)
{
    const float* x   = (const float*)d_in[0];
    const int*   ei  = (const int*)d_in[1];
    const float* W1  = (const float*)d_in[2];
    const float* as1 = (const float*)d_in[3];
    const float* ad1 = (const float*)d_in[4];
    const float* b1  = (const float*)d_in[5];
    const float* W2  = (const float*)d_in[6];
    const float* as2 = (const float*)d_in[7];
    const float* ad2 = (const float*)d_in[8];
    const float* b2  = (const float*)d_in[9];
    const float* W3  = (const float*)d_in[10];
    const float* as3 = (const float*)d_in[11];
    const float* ad3 = (const float*)d_in[12];
    const float* b3  = (const float*)d_in[13];
    float* out = (float*)d_out;

    float *bufA, *bufB, *h3;
    cudaGetSymbolAddress((void**)&bufA, g_bufA);
    cudaGetSymbolAddress((void**)&bufB, g_bufB);
    cudaGetSymbolAddress((void**)&h3,   g_h3);
    __half* hA = (__half*)bufA;

    cudaFuncSetAttribute(k_gemm128_mma,
                         cudaFuncAttributeMaxDynamicSharedMemorySize, GEMM_SMEM);

    const int T = 256;
    const int gGemm = (NN + 127) / 128;
    const int gWarp = (NN * 32 + T - 1) / T;
    const int gQuad = (NN * 4 + T - 1) / T;

    // 1-3: setup + CSR phase 1
    k_setup<<<(NN + T - 1) / T, T>>>(ei, W1, W2);
    k_convert<<<(NE + T - 1) / T, T>>>(ei);
    k_scan1<<<NSCANB, SCAN_B>>>();
    // 4: layer-1 GEMM (profiled slot)
    k_gemm128_mma<<<gGemm, T, GEMM_SMEM>>>(x, hA, NN, as1, ad1, 0);
    // 5-6: finish CSR
    k_scan3<<<(NN + T - 1) / T, T>>>();
    k_fill<<<(NE + T - 1) / T, T>>>();
    // layer 1 aggregate
    k_gather128<true><<<gWarp, T>>>(hA, bufB, b1);
    // layer 2
    k_gemm128_mma<<<gGemm, T, GEMM_SMEM>>>(bufB, hA, NN, as2, ad2, 1);
    k_gather128<true><<<gWarp, T>>>(hA, bufB, b2);
    // layer 3 (fp32)
    k_gemm16<<<(NN + 63) / 64, T>>>(bufB, W3, h3, NN, as3, ad3);
    k_gather16<<<gQuad, T>>>(h3, out, b3);
}

// round 16
// speedup vs baseline: 1.4467x; 1.0555x over previous
#include <cuda_runtime.h>
#include <cuda_bf16.h>
#include <cuda_fp16.h>
#include <cstdint>

#define NN   50000
#define NE   800000
#define FDIM 128
#define FOUT 16
#define NEG  0.2f
#define SCAN_B 512
#define NSCANB ((NN + SCAN_B - 1) / SCAN_B)   // 98

// gemm smem layout (bytes): A row stride = 136 bf16 = 272 B
#define SA_HI 0
#define SA_LO 34816
#define SB_HI 69632
#define SB_LO 102400
#define GEMM_SMEM 135168

// ---------------- scratch ----------------
__device__ __align__(16) float g_bufA[NN * FDIM];   // layer1/2 h stored as fp16 (reinterpreted)
__device__ __align__(16) float g_bufB[NN * FDIM];
__device__ __align__(16) float g_h3[NN * FOUT];
__device__ __align__(16) float g_es[NN * 4];
__device__ __align__(16) float g_ed[NN * 4];
__device__ __align__(16) uint32_t g_wfHi[16384];   // W fragments (2 layers), hi bf16
__device__ __align__(16) uint32_t g_wfLo[16384];   // W fragments (2 layers), lo bf16
__device__ int g_src[NE];
__device__ int g_dst[NE];
__device__ int g_deg[NN];
__device__ int g_rowptr[NN + 1];
__device__ int g_cursor[NN];
__device__ int g_csrc[NE];
__device__ int g_bsum[128];
__device__ int g_is32;

__device__ __forceinline__ uint32_t smem_u32(const void* p) {
    uint32_t a;
    asm("{ .reg .u64 t; cvta.to.shared.u64 t, %1; cvt.u32.u64 %0, t; }"
        : "=r"(a) : "l"(p));
    return a;
}

__device__ __forceinline__ void split2(float x, float y, uint32_t& h, uint32_t& l) {
    __nv_bfloat16 hx = __float2bfloat16(x), hy = __float2bfloat16(y);
    __nv_bfloat16 lx = __float2bfloat16(x - __bfloat162float(hx));
    __nv_bfloat16 ly = __float2bfloat16(y - __bfloat162float(hy));
    h = ((uint32_t)__bfloat16_as_ushort(hy) << 16) | __bfloat16_as_ushort(hx);
    l = ((uint32_t)__bfloat16_as_ushort(ly) << 16) | __bfloat16_as_ushort(lx);
}

__device__ __forceinline__ void mma_bf16(float* c, const uint32_t* a, uint32_t b0, uint32_t b1) {
    asm volatile(
        "mma.sync.aligned.m16n8k16.row.col.f32.bf16.bf16.f32 "
        "{%0,%1,%2,%3}, {%4,%5,%6,%7}, {%8,%9}, {%0,%1,%2,%3};"
        : "+f"(c[0]), "+f"(c[1]), "+f"(c[2]), "+f"(c[3])
        : "r"(a[0]), "r"(a[1]), "r"(a[2]), "r"(a[3]), "r"(b0), "r"(b1));
}

// ---- setup: zero degree + dtype detect + pack W1/W2 mma fragments ----
__global__ void k_setup(const int* __restrict__ ei,
                        const float* __restrict__ W1, const float* __restrict__ W2)
{
    int i = blockIdx.x * blockDim.x + threadIdx.x;
    if (i < NN) g_deg[i] = 0;
    if (i == 0) {
        int nz = 0;
#pragma unroll
        for (int t = 0; t < 16; t++) nz |= ei[2 * t + 1];
        g_is32 = (nz != 0);
    }
    if (i < 16384) {
        const float* W = (i < 8192) ? W1 : W2;
        int idx = i & 8191;
        int reg = idx & 1, lane = (idx >> 1) & 31;
        int rest = idx >> 6, nb = rest & 15, ks = rest >> 4;
        int g = lane >> 2, t = lane & 3;
        int n = nb * 8 + g;
        int k0 = ks * 16 + 2 * t + reg * 8;
        float w0 = W[k0 * 128 + n];
        float w1 = W[(k0 + 1) * 128 + n];
        uint32_t h, l;
        split2(w0, w1, h, l);
        g_wfHi[i] = h;
        g_wfLo[i] = l;
    }
}

__global__ void k_convert(const int* __restrict__ ei) {
    int e = blockIdx.x * blockDim.x + threadIdx.x;
    if (e >= NE) return;
    int s, d;
    if (g_is32) {
        s = ei[e]; d = ei[NE + e];
    } else {
        const long long* ell = (const long long*)ei;
        s = (int)ell[e]; d = (int)ell[NE + e];
    }
    g_src[e] = s;
    g_dst[e] = d;
    atomicAdd(&g_deg[d], 1);
}

// ---------------- exclusive scan ----------------
__global__ void k_scan1() {
    __shared__ int sm[SCAN_B];
    int i = blockIdx.x * SCAN_B + threadIdx.x;
    int v = (i < NN) ? g_deg[i] : 0;
    sm[threadIdx.x] = v;
    __syncthreads();
#pragma unroll
    for (int off = 1; off < SCAN_B; off <<= 1) {
        int t = (threadIdx.x >= off) ? sm[threadIdx.x - off] : 0;
        __syncthreads();
        sm[threadIdx.x] += t;
        __syncthreads();
    }
    if (i < NN) g_rowptr[i] = sm[threadIdx.x] - v;
    if (threadIdx.x == SCAN_B - 1) g_bsum[blockIdx.x] = sm[SCAN_B - 1];
}

__global__ void k_scan3() {
    __shared__ int pre[NSCANB];
    if (threadIdx.x < NSCANB) pre[threadIdx.x] = g_bsum[threadIdx.x];
    __syncthreads();
    if (threadIdx.x == 0) {
        int run = 0;
#pragma unroll 1
        for (int b = 0; b < NSCANB; b++) { int t = pre[b]; pre[b] = run; run += t; }
    }
    __syncthreads();
    int i = blockIdx.x * blockDim.x + threadIdx.x;
    if (i < NN) {
        int v = g_rowptr[i] + pre[i / SCAN_B];
        g_rowptr[i] = v;
        g_cursor[i] = v;
    }
    if (i == 0) g_rowptr[NN] = NE;
}

__global__ void k_fill() {
    int e = blockIdx.x * blockDim.x + threadIdx.x;
    if (e >= NE) return;
    int pos = atomicAdd(&g_cursor[g_dst[e]], 1);
    g_csrc[pos] = g_src[e];
}

// ------- tensor-core GEMM: h(fp16)[M,128] = A[M,128] @ W; bf16 split 3-product
// Single ks-loop: A hi+lo frags loaded once, 6 mma per B hi/lo pair.
__global__ __launch_bounds__(256, 1) void k_gemm128_mma(
    const float* __restrict__ A, __half* __restrict__ C, int M,
    const float* __restrict__ a_s, const float* __restrict__ a_d, int slot)
{
    extern __shared__ char smem[];
    const int tid = threadIdx.x;
    const int rowBase = blockIdx.x * 128;

    // ---- B fragments: async copy from gmem (overlaps A load/convert) ----
    {
        uint32_t dH = smem_u32(smem + SB_HI) + tid * 16;
        uint32_t dL = smem_u32(smem + SB_LO) + tid * 16;
        const char* sH = (const char*)(g_wfHi + slot * 8192) + tid * 16;
        const char* sL = (const char*)(g_wfLo + slot * 8192) + tid * 16;
#pragma unroll
        for (int q = 0; q < 8; q++) {
            asm volatile("cp.async.cg.shared.global [%0], [%1], 16;"
                         :: "r"(dH + q * 4096), "l"(sH + q * 4096));
            asm volatile("cp.async.cg.shared.global [%0], [%1], 16;"
                         :: "r"(dL + q * 4096), "l"(sL + q * 4096));
        }
        asm volatile("cp.async.commit_group;");
    }

    // ---- load A tile, split into hi/lo bf16, padded rows (272B stride) ----
    {
        int r = tid & 127, half = tid >> 7;
        int gr = rowBase + r;
        const float* Ap = A + (long)gr * 128 + half * 64;
        char* ah = smem + SA_HI + r * 272 + half * 128;
        char* al = smem + SA_LO + r * 272 + half * 128;
#pragma unroll
        for (int q = 0; q < 8; q++) {
            float4 f0 = (gr < M) ? *(const float4*)(Ap + q * 8)     : make_float4(0,0,0,0);
            float4 f1 = (gr < M) ? *(const float4*)(Ap + q * 8 + 4) : make_float4(0,0,0,0);
            uint4 h, l;
            split2(f0.x, f0.y, h.x, l.x);
            split2(f0.z, f0.w, h.y, l.y);
            split2(f1.x, f1.y, h.z, l.z);
            split2(f1.z, f1.w, h.w, l.w);
            *(uint4*)(ah + q * 16) = h;
            *(uint4*)(al + q * 16) = l;
        }
    }
    asm volatile("cp.async.wait_group 0;" ::: "memory");
    __syncthreads();

    const int w = tid >> 5, lane = tid & 31;
    const int g = lane >> 2, t = lane & 3;
    const int mrow = (w >> 1) * 32;
    const int nbB  = (w & 1) * 8;

    float acc[2][8][4];
#pragma unroll
    for (int mb = 0; mb < 2; mb++)
#pragma unroll
        for (int nb = 0; nb < 8; nb++)
#pragma unroll
            for (int q = 0; q < 4; q++) acc[mb][nb][q] = 0.f;

#pragma unroll
    for (int ks = 0; ks < 8; ks++) {
        uint32_t ah[2][4], al[2][4];
        const int kb = (ks * 16 + 2 * t) * 2;
#pragma unroll
        for (int mb = 0; mb < 2; mb++) {
            int r0 = mrow + mb * 16 + g;
            ah[mb][0] = *(const uint32_t*)(smem + SA_HI + r0 * 272 + kb);
            ah[mb][1] = *(const uint32_t*)(smem + SA_HI + (r0 + 8) * 272 + kb);
            ah[mb][2] = *(const uint32_t*)(smem + SA_HI + r0 * 272 + kb + 16);
            ah[mb][3] = *(const uint32_t*)(smem + SA_HI + (r0 + 8) * 272 + kb + 16);
            al[mb][0] = *(const uint32_t*)(smem + SA_LO + r0 * 272 + kb);
            al[mb][1] = *(const uint32_t*)(smem + SA_LO + (r0 + 8) * 272 + kb);
            al[mb][2] = *(const uint32_t*)(smem + SA_LO + r0 * 272 + kb + 16);
            al[mb][3] = *(const uint32_t*)(smem + SA_LO + (r0 + 8) * 272 + kb + 16);
        }
#pragma unroll
        for (int nb = 0; nb < 8; nb++) {
            int boff = ((ks * 16 + nbB + nb) * 32 + lane) * 8;
            uint2 bh = *(const uint2*)(smem + SB_HI + boff);
            uint2 bl = *(const uint2*)(smem + SB_LO + boff);
            mma_bf16(acc[0][nb], ah[0], bh.x, bh.y);
            mma_bf16(acc[1][nb], ah[1], bh.x, bh.y);
            mma_bf16(acc[0][nb], ah[0], bl.x, bl.y);
            mma_bf16(acc[1][nb], ah[1], bl.x, bl.y);
            mma_bf16(acc[0][nb], al[0], bh.x, bh.y);
            mma_bf16(acc[1][nb], al[1], bh.x, bh.y);
        }
    }

    // ---- epilogue: store C (fp16) + fused es/ed (from fp32 accs) ----
    float es[2][2][2], ed[2][2][2];
#pragma unroll
    for (int mb = 0; mb < 2; mb++)
#pragma unroll
        for (int rh = 0; rh < 2; rh++)
#pragma unroll
            for (int h = 0; h < 2; h++) { es[mb][rh][h] = 0.f; ed[mb][rh][h] = 0.f; }

#pragma unroll
    for (int mb = 0; mb < 2; mb++) {
        int r0 = rowBase + mrow + mb * 16 + g;
        int r1 = r0 + 8;
#pragma unroll
        for (int nb = 0; nb < 8; nb++) {
            int col = (w & 1) * 64 + nb * 8 + 2 * t;
            int h = nb >> 2;
            float c0 = acc[mb][nb][0], c1 = acc[mb][nb][1];
            float c2 = acc[mb][nb][2], c3 = acc[mb][nb][3];
            if (r0 < M) *(__half2*)(C + (long)r0 * 128 + col) = __floats2half2_rn(c0, c1);
            if (r1 < M) *(__half2*)(C + (long)r1 * 128 + col) = __floats2half2_rn(c2, c3);
            float as0 = a_s[col], as1 = a_s[col + 1];
            float ad0 = a_d[col], ad1 = a_d[col + 1];
            es[mb][0][h] += c0 * as0 + c1 * as1;
            es[mb][1][h] += c2 * as0 + c3 * as1;
            ed[mb][0][h] += c0 * ad0 + c1 * ad1;
            ed[mb][1][h] += c2 * ad0 + c3 * ad1;
        }
    }
#pragma unroll
    for (int mb = 0; mb < 2; mb++)
#pragma unroll
        for (int rh = 0; rh < 2; rh++)
#pragma unroll
            for (int h = 0; h < 2; h++) {
                float s = es[mb][rh][h], d = ed[mb][rh][h];
                s += __shfl_xor_sync(0xffffffff, s, 1);
                d += __shfl_xor_sync(0xffffffff, d, 1);
                s += __shfl_xor_sync(0xffffffff, s, 2);
                d += __shfl_xor_sync(0xffffffff, d, 2);
                if (t == 0) {
                    int row = rowBase + mrow + mb * 16 + rh * 8 + g;
                    if (row < M) {
                        int head = (w & 1) * 2 + h;
                        g_es[row * 4 + head] = s;
                        g_ed[row * 4 + head] = d;
                    }
                }
            }
}

// ---------------- layer-3 GEMM + fused attn (H=1, C=16), fp32 ----------------
__global__ __launch_bounds__(256) void k_gemm16(
    const float* __restrict__ A, const float* __restrict__ W,
    float* __restrict__ C, int M,
    const float* __restrict__ a_s, const float* __restrict__ a_d)
{
    __shared__ float Ws[128 * 16];
    int tid = threadIdx.x;
    for (int i = tid * 4; i < 2048; i += 1024)
        *(float4*)&Ws[i] = *(const float4*)(W + i);
    __syncthreads();
    int row = blockIdx.x * 64 + (tid >> 2);
    int c4 = (tid & 3) * 4;
    if (row >= M) return;
    const float* Ap = A + (long)row * 128;
    float4 acc = make_float4(0, 0, 0, 0);
#pragma unroll 8
    for (int k = 0; k < 128; k += 4) {
        float4 a = *(const float4*)(Ap + k);
#pragma unroll
        for (int kk = 0; kk < 4; kk++) {
            float av = (&a.x)[kk];
            float4 w = *(const float4*)&Ws[(k + kk) * 16 + c4];
            acc.x += av * w.x; acc.y += av * w.y;
            acc.z += av * w.z; acc.w += av * w.w;
        }
    }
    *(float4*)(C + (long)row * 16 + c4) = acc;

    float4 u = *(const float4*)(a_s + c4);
    float4 v = *(const float4*)(a_d + c4);
    float s = acc.x * u.x + acc.y * u.y + acc.z * u.z + acc.w * u.w;
    float d = acc.x * v.x + acc.y * v.y + acc.z * v.z + acc.w * v.w;
    s += __shfl_xor_sync(0xffffffff, s, 1);
    d += __shfl_xor_sync(0xffffffff, d, 1);
    s += __shfl_xor_sync(0xffffffff, s, 2);
    d += __shfl_xor_sync(0xffffffff, d, 2);
    if ((tid & 3) == 0) { g_es[row] = s; g_ed[row] = d; }
}

// ------- fused gather, warp per dst; h is fp16; csrc batched via shfl -------
template<bool RELU>
__global__ void k_gather128(const __half* __restrict__ h, float* __restrict__ o,
                            const float* __restrict__ bias)
{
    int w = (blockIdx.x * blockDim.x + threadIdx.x) >> 5;
    int lane = threadIdx.x & 31;
    if (w >= NN) return;
    int head = lane >> 3;
    float edh = g_ed[w * 4 + head];
    float denom = 0.f;
    float4 acc = make_float4(0, 0, 0, 0);
    {
        float v = g_es[w * 4 + head] + edh;
        v = (v > 0.f) ? v : NEG * v;
        float p = __expf(v);
        denom += p;
        uint2 raw = *(const uint2*)(h + (long)w * 128 + lane * 4);
        float2 f01 = __half22float2(*(__half2*)&raw.x);
        float2 f23 = __half22float2(*(__half2*)&raw.y);
        acc.x += p * f01.x; acc.y += p * f01.y; acc.z += p * f23.x; acc.w += p * f23.y;
    }
    int j = g_rowptr[w], end = g_rowptr[w + 1];
    while (j < end) {
        int rem = end - j;
        int batch = rem < 32 ? rem : 32;
        int s_l = (lane < batch) ? g_csrc[j + lane] : 0;
        int t = 0;
        for (; t + 2 <= batch; t += 2) {
            int s0 = __shfl_sync(0xffffffff, s_l, t);
            int s1 = __shfl_sync(0xffffffff, s_l, t + 1);
            float v0 = g_es[s0 * 4 + head] + edh;
            float v1 = g_es[s1 * 4 + head] + edh;
            uint2 r0 = *(const uint2*)(h + (long)s0 * 128 + lane * 4);
            uint2 r1 = *(const uint2*)(h + (long)s1 * 128 + lane * 4);
            v0 = (v0 > 0.f) ? v0 : NEG * v0;
            v1 = (v1 > 0.f) ? v1 : NEG * v1;
            float p0 = __expf(v0), p1 = __expf(v1);
            denom += p0 + p1;
            float2 a01 = __half22float2(*(__half2*)&r0.x);
            float2 a23 = __half22float2(*(__half2*)&r0.y);
            float2 b01 = __half22float2(*(__half2*)&r1.x);
            float2 b23 = __half22float2(*(__half2*)&r1.y);
            acc.x += p0 * a01.x + p1 * b01.x;
            acc.y += p0 * a01.y + p1 * b01.y;
            acc.z += p0 * a23.x + p1 * b23.x;
            acc.w += p0 * a23.y + p1 * b23.y;
        }
        if (t < batch) {
            int s = __shfl_sync(0xffffffff, s_l, t);
            float v = g_es[s * 4 + head] + edh;
            v = (v > 0.f) ? v : NEG * v;
            float p = __expf(v);
            denom += p;
            uint2 raw = *(const uint2*)(h + (long)s * 128 + lane * 4);
            float2 f01 = __half22float2(*(__half2*)&raw.x);
            float2 f23 = __half22float2(*(__half2*)&raw.y);
            acc.x += p * f01.x; acc.y += p * f01.y; acc.z += p * f23.x; acc.w += p * f23.y;
        }
        j += batch;
    }
    float inv = 1.f / (denom + 1e-16f);
    float4 b = *(const float4*)(bias + lane * 4);
    float4 r;
    r.x = acc.x * inv + b.x; r.y = acc.y * inv + b.y;
    r.z = acc.z * inv + b.z; r.w = acc.w * inv + b.w;
    if (RELU) {
        r.x = fmaxf(r.x, 0.f); r.y = fmaxf(r.y, 0.f);
        r.z = fmaxf(r.z, 0.f); r.w = fmaxf(r.w, 0.f);
    }
    *(float4*)(o + (long)w * 128 + lane * 4) = r;
}

// ---- fused gather (F=16, H=1): quad per dst, fp32 h ------------------------
__global__ void k_gather16(const float* __restrict__ h, float* __restrict__ o,
                           const float* __restrict__ bias)
{
    int g = blockIdx.x * blockDim.x + threadIdx.x;
    int n = g >> 2, q = g & 3;
    if (n >= NN) return;
    int lane = threadIdx.x & 31;
    int qbase = lane & 28;
    unsigned qmask = 0xFu << qbase;
    float edh = g_ed[n];
    float denom = 0.f;
    float4 acc = make_float4(0, 0, 0, 0);
    {
        float v = g_es[n] + edh;
        v = (v > 0.f) ? v : NEG * v;
        float p = __expf(v);
        denom += p;
        float4 hv = *(const float4*)(h + (long)n * 16 + q * 4);
        acc.x += p * hv.x; acc.y += p * hv.y; acc.z += p * hv.z; acc.w += p * hv.w;
    }
    int j = g_rowptr[n], end = g_rowptr[n + 1];
    while (j < end) {
        int rem = end - j;
        int batch = rem < 4 ? rem : 4;
        int s_l = (q < batch) ? g_csrc[j + q] : 0;
#pragma unroll 4
        for (int t = 0; t < batch; t++) {
            int s = __shfl_sync(qmask, s_l, qbase + t);
            float v = g_es[s] + edh;
            v = (v > 0.f) ? v : NEG * v;
            float p = __expf(v);
            denom += p;
            float4 hv = *(const float4*)(h + (long)s * 16 + q * 4);
            acc.x += p * hv.x; acc.y += p * hv.y; acc.z += p * hv.z; acc.w += p * hv.w;
        }
        j += batch;
    }
    float inv = 1.f / (denom + 1e-16f);
    float4 b = *(const float4*)(bias + q * 4);
    float4 r;
    r.x = acc.x * inv + b.x; r.y = acc.y * inv + b.y;
    r.z = acc.z * inv + b.z; r.w = acc.w * inv + b.w;
    *(float4*)(o + (long)n * 16 + q * 4) = r;
}

// ---------------- launch ----------------
extern "C" void kernel_launch(void* const* d_in, const int* in_sizes, int n_in,
                              void* d_out, int out_size)
{
    const float* x   = (const float*)d_in[0];
    const int*   ei  = (const int*)d_in[1];
    const float* W1  = (const float*)d_in[2];
    const float* as1 = (const float*)d_in[3];
    const float* ad1 = (const float*)d_in[4];
    const float* b1  = (const float*)d_in[5];
    const float* W2  = (const float*)d_in[6];
    const float* as2 = (const float*)d_in[7];
    const float* ad2 = (const float*)d_in[8];
    const float* b2  = (const float*)d_in[9];
    const float* W3  = (const float*)d_in[10];
    const float* as3 = (const float*)d_in[11];
    const float* ad3 = (const float*)d_in[12];
    const float* b3  = (const float*)d_in[13];
    float* out = (float*)d_out;

    float *bufA, *bufB, *h3;
    cudaGetSymbolAddress((void**)&bufA, g_bufA);
    cudaGetSymbolAddress((void**)&bufB, g_bufB);
    cudaGetSymbolAddress((void**)&h3,   g_h3);
    __half* hA = (__half*)bufA;

    cudaFuncSetAttribute(k_gemm128_mma,
                         cudaFuncAttributeMaxDynamicSharedMemorySize, GEMM_SMEM);

    const int T = 256;
    const int gGemm = (NN + 127) / 128;
    const int gWarp = (NN * 32 + T - 1) / T;
    const int gQuad = (NN * 4 + T - 1) / T;

    // 1-3: setup + CSR phase 1
    k_setup<<<(NN + T - 1) / T, T>>>(ei, W1, W2);
    k_convert<<<(NE + T - 1) / T, T>>>(ei);
    k_scan1<<<NSCANB, SCAN_B>>>();
    // 4: layer-1 GEMM (profiled slot)
    k_gemm128_mma<<<gGemm, T, GEMM_SMEM>>>(x, hA, NN, as1, ad1, 0);
    // 5-6: finish CSR
    k_scan3<<<(NN + T - 1) / T, T>>>();
    k_fill<<<(NE + T - 1) / T, T>>>();
    // layer 1 aggregate
    k_gather128<true><<<gWarp, T>>>(hA, bufB, b1);
    // layer 2
    k_gemm128_mma<<<gGemm, T, GEMM_SMEM>>>(bufB, hA, NN, as2, ad2, 1);
    k_gather128<true><<<gWarp, T>>>(hA, bufB, b2);
    // layer 3 (fp32)
    k_gemm16<<<(NN + 63) / 64, T>>>(bufB, W3, h3, NN, as3, ad3);
    k_gather16<<<gQuad, T>>>(h3, out, b3);
}